// round 3
// baseline (speedup 1.0000x reference)
#include <cuda_runtime.h>
#include <cstdint>
#include <math.h>

#define NB 128
#define NTOK 577
#define NP 576
#define DD 768
#define NG 17
#define NGC 18          // 17 groups + cls row
#define NOCC 10
#define THREADS 576
#define NCOMP 288       // compute threads for phase 1 (T=2 patches each)
#define TILE_D 32       // d-chunk per tile (128B rows)
#define NTILES (DD / TILE_D)   // 24

typedef unsigned long long ull;

// ---- packed f32x2 helpers (sm_103a) ----
__device__ __forceinline__ ull pk2(float a, float b) {
    ull r; asm("mov.b64 %0, {%1,%2};" : "=l"(r) : "f"(a), "f"(b)); return r;
}
__device__ __forceinline__ void fma2(ull &acc, ull a, ull b) {
    asm("fma.rn.f32x2 %0, %1, %2, %0;" : "+l"(acc) : "l"(a), "l"(b));
}
__device__ __forceinline__ float hadd2(ull a) {
    return __uint_as_float((unsigned)a) + __uint_as_float((unsigned)(a >> 32));
}

// SW128-style swizzle on 128B rows: float index of 16B-block `blk` in row `r`
__device__ __forceinline__ int swz(int r, int blk) {
    return r * TILE_D + ((blk ^ (r & 7)) << 2);
}

// shared-memory layout (floats)
// x tile buffers: 576 rows x 32 floats each
#define OFF_X0   0                       // 18432 floats (73728 B)
#define OFF_X1   18432                   // 18432 floats
#define OFF_WT   36864                   // 18*768 = 13824 ([g][d], g=17 is cls)
#define OFF_SIM  50688                   // 576
#define OFF_MASK 51264                   // 576
#define SMEM_FLOATS 51840                // 207360 B
// s_sc (17*576 = 9792 floats) aliases OFF_X0 after phase 1

extern __shared__ float sm[];

__global__ void __launch_bounds__(THREADS, 1)
oag_kernel(const float* __restrict__ x, const float* __restrict__ gw,
           float* __restrict__ out) {
    const int b   = blockIdx.x;
    const int tid = threadIdx.x;

    float* s_x[2] = { sm + OFF_X0, sm + OFF_X1 };
    float* s_wt   = sm + OFF_WT;
    float* s_sim  = sm + OFF_SIM;
    float* s_mask = sm + OFF_MASK;
    float* s_sc   = sm + OFF_X0;   // alias, live after phase 1

    const size_t xb = (size_t)b * NTOK * DD;

    // ---- phase 0: stage W^T ([g][d]) + cls as group 17 ----
    for (int i = tid; i < DD * NG; i += THREADS) {
        int d = i / NG, g = i % NG;
        s_wt[g * DD + d] = gw[i];
    }
    for (int i = tid; i < DD; i += THREADS) s_wt[NG * DD + i] = x[xb + i];
    if (tid < NP) s_mask[tid] = 1.0f;

    const bool is_comp = (tid < NCOMP);
    const int  j       = tid - NCOMP;    // loader index 0..287

    // loaders prefetch tile 0 (no barrier needed before: buffers untouched yet)
    if (!is_comp) {
#pragma unroll
        for (int k = 0; k < 16; ++k) {
            int i = j + 288 * k;
            int row = i >> 3, blk = i & 7;
            float4 v = *reinterpret_cast<const float4*>(
                x + xb + (size_t)(1 + row) * DD + blk * 4);
            *reinterpret_cast<float4*>(s_x[0] + swz(row, blk)) = v;
        }
    }
    __syncthreads();

    // ---- phase 1: tiled GEMM. compute threads: patches p0=tid, p1=tid+288 ----
    ull a0[NG], a1[NG], c0 = 0, c1 = 0, n0 = 0, n1 = 0;
#pragma unroll
    for (int g = 0; g < NG; ++g) { a0[g] = 0; a1[g] = 0; }

    for (int t = 0; t < NTILES; ++t) {
        const float* xt = s_x[t & 1];
        if (!is_comp) {
            if (t + 1 < NTILES) {
                float* dst = s_x[(t + 1) & 1];
                const int d0n = (t + 1) * TILE_D;
#pragma unroll
                for (int k = 0; k < 16; ++k) {
                    int i = j + 288 * k;
                    int row = i >> 3, blk = i & 7;
                    float4 v = *reinterpret_cast<const float4*>(
                        x + xb + (size_t)(1 + row) * DD + d0n + blk * 4);
                    *reinterpret_cast<float4*>(dst + swz(row, blk)) = v;
                }
            }
        } else {
            const int p0 = tid, p1 = tid + NCOMP;
            const int d0 = t * TILE_D;
#pragma unroll
            for (int blk = 0; blk < 8; ++blk) {
                ulonglong2 xv0 = *reinterpret_cast<const ulonglong2*>(xt + swz(p0, blk));
                ulonglong2 xv1 = *reinterpret_cast<const ulonglong2*>(xt + swz(p1, blk));
                const float* wd = s_wt + d0 + blk * 4;
#pragma unroll
                for (int g = 0; g < NG; ++g) {
                    ulonglong2 w = *reinterpret_cast<const ulonglong2*>(wd + g * DD);
                    fma2(a0[g], xv0.x, w.x); fma2(a0[g], xv0.y, w.y);
                    fma2(a1[g], xv1.x, w.x); fma2(a1[g], xv1.y, w.y);
                }
                ulonglong2 wc = *reinterpret_cast<const ulonglong2*>(wd + NG * DD);
                fma2(c0, xv0.x, wc.x); fma2(c0, xv0.y, wc.y);
                fma2(c1, xv1.x, wc.x); fma2(c1, xv1.y, wc.y);
                fma2(n0, xv0.x, xv0.x); fma2(n0, xv0.y, xv0.y);
                fma2(n1, xv1.x, xv1.x); fma2(n1, xv1.y, xv1.y);
            }
        }
        __syncthreads();
    }

    // write scores + sim (s_sc aliases x-buffer 0; all reads of it are done)
    if (is_comp) {
        const int p0 = tid, p1 = tid + NCOMP;
#pragma unroll
        for (int g = 0; g < NG; ++g) {
            s_sc[g * NP + p0] = hadd2(a0[g]);
            s_sc[g * NP + p1] = hadd2(a1[g]);
        }
        // cls-norm factor dropped: positive per-batch constant, ordering-invariant
        s_sim[p0] = hadd2(c0) / fmaxf(sqrtf(hadd2(n0)), 1e-12f);
        s_sim[p1] = hadd2(c1) / fmaxf(sqrtf(hadd2(n1)), 1e-12f);
    }
    __syncthreads();

    // ---- phase 2: 10x argmin within warp 0 (tie -> lower index) ----
    if (tid < 32) {
        for (int k = 0; k < NOCC; ++k) {
            float best = 3.4e38f; int bi = NP;
#pragma unroll
            for (int q = 0; q < NP / 32; ++q) {
                int idx = tid + q * 32;
                float v = s_sim[idx];
                if (v < best || (v == best && idx < bi)) { best = v; bi = idx; }
            }
#pragma unroll
            for (int off = 16; off; off >>= 1) {
                float ov = __shfl_down_sync(0xffffffffu, best, off);
                int   oi = __shfl_down_sync(0xffffffffu, bi, off);
                if (ov < best || (ov == best && oi < bi)) { best = ov; bi = oi; }
            }
            bi = __shfl_sync(0xffffffffu, bi, 0);
            if (tid == 0) { s_sim[bi] = 3.4e38f; s_mask[bi] = 0.0f; }
            __syncwarp();
        }
    }
    __syncthreads();

    // ---- phase 3: softmax over g; masked -> attn 1/17 (out), weight 0 (smem) ----
    if (tid < NP) {
        const int p = tid;
        const float mk = s_mask[p];
        float tv[NG];
        float m = -3.4e38f;
#pragma unroll
        for (int g = 0; g < NG; ++g) {
            tv[g] = s_sc[g * NP + p] * 10.0f;
            m = fmaxf(m, tv[g]);
        }
        float ssum = 0.f;
#pragma unroll
        for (int g = 0; g < NG; ++g) { tv[g] = __expf(tv[g] - m); ssum += tv[g]; }
        const float inv = 1.0f / ssum;
        float* oat = out + (size_t)NB * NGC * DD + (size_t)b * NG * NP;
#pragma unroll
        for (int g = 0; g < NG; ++g) {
            float a = tv[g] * inv;
            oat[g * NP + p] = (mk != 0.f) ? a : (1.0f / 17.0f);
            s_sc[g * NP + p] = (mk != 0.f) ? a : 0.f;
        }
    }
    __syncthreads();

    // ---- phase E: group_features, T=2 columns per thread (384 threads) ----
    if (tid < 384) {
        const int d0 = tid, d1 = tid + 384;
        const float* xp0 = x + xb + DD + d0;
        const float* xp1 = x + xb + DD + d1;
        ull A0[NG], A1[NG];
#pragma unroll
        for (int g = 0; g < NG; ++g) { A0[g] = 0; A1[g] = 0; }

        // rolling prefetch, 4 patches per step
        float c00 = xp0[0], c01 = xp0[(size_t)1 * DD], c02 = xp0[(size_t)2 * DD], c03 = xp0[(size_t)3 * DD];
        float c10 = xp1[0], c11 = xp1[(size_t)1 * DD], c12 = xp1[(size_t)2 * DD], c13 = xp1[(size_t)3 * DD];

        for (int p4 = 0; p4 < NP; p4 += 4) {
            float n00 = 0, n01 = 0, n02 = 0, n03 = 0, n10 = 0, n11 = 0, n12 = 0, n13 = 0;
            if (p4 + 4 < NP) {
                n00 = xp0[(size_t)(p4 + 4) * DD]; n01 = xp0[(size_t)(p4 + 5) * DD];
                n02 = xp0[(size_t)(p4 + 6) * DD]; n03 = xp0[(size_t)(p4 + 7) * DD];
                n10 = xp1[(size_t)(p4 + 4) * DD]; n11 = xp1[(size_t)(p4 + 5) * DD];
                n12 = xp1[(size_t)(p4 + 6) * DD]; n13 = xp1[(size_t)(p4 + 7) * DD];
            }
            ull x0a = pk2(c00, c01), x0b = pk2(c02, c03);
            ull x1a = pk2(c10, c11), x1b = pk2(c12, c13);
            const float* ap = s_sc + p4;
#pragma unroll
            for (int g = 0; g < NG; ++g) {
                ulonglong2 at = *reinterpret_cast<const ulonglong2*>(ap + g * NP);
                fma2(A0[g], x0a, at.x); fma2(A0[g], x0b, at.y);
                fma2(A1[g], x1a, at.x); fma2(A1[g], x1b, at.y);
            }
            c00 = n00; c01 = n01; c02 = n02; c03 = n03;
            c10 = n10; c11 = n11; c12 = n12; c13 = n13;
        }

        float* ob = out + (size_t)b * NGC * DD;
        ob[d0] = s_wt[NG * DD + d0];   // feats[b][0][*] = cls
        ob[d1] = s_wt[NG * DD + d1];
#pragma unroll
        for (int g = 0; g < NG; ++g) {
            ob[(size_t)(1 + g) * DD + d0] = hadd2(A0[g]);
            ob[(size_t)(1 + g) * DD + d1] = hadd2(A1[g]);
        }
    }
}

extern "C" void kernel_launch(void* const* d_in, const int* in_sizes, int n_in,
                              void* d_out, int out_size) {
    const float* x  = (const float*)d_in[0];
    const float* gw = (const float*)d_in[1];
    float* out = (float*)d_out;
    size_t smem = SMEM_FLOATS * sizeof(float);
    cudaFuncSetAttribute(oag_kernel, cudaFuncAttributeMaxDynamicSharedMemorySize,
                         (int)smem);
    oag_kernel<<<NB, THREADS, smem>>>(x, gw, out);
}

// round 4
// speedup vs baseline: 1.4740x; 1.4740x over previous
#include <cuda_runtime.h>
#include <cstdint>
#include <math.h>

#define NB 128
#define NTOK 577
#define NP 576
#define DD 768
#define NG 17
#define NGC 18          // 17 groups + cls row
#define NOCC 10

typedef unsigned long long ull;

// ---- packed f32x2 helpers (sm_103a) ----
__device__ __forceinline__ ull pk2(float a, float b) {
    ull r; asm("mov.b64 %0, {%1,%2};" : "=l"(r) : "f"(a), "f"(b)); return r;
}
__device__ __forceinline__ void fma2(ull &acc, ull a, ull b) {
    asm("fma.rn.f32x2 %0, %1, %2, %0;" : "+l"(acc) : "l"(a), "l"(b));
}
__device__ __forceinline__ float hadd2(ull a) {
    return __uint_as_float((unsigned)a) + __uint_as_float((unsigned)(a >> 32));
}

// scratch (device globals; no allocation)
__device__ float g_scores[(size_t)NB * NG * NP];   // raw scores, then masked attn
__device__ float g_sim[(size_t)NB * NP];

// ============================ K1: scores + sim ============================
// grid (NB, 3), block 192. Each thread owns one patch p = by*192+tid.
// smem: W^T [18][768] (g=17 is cls row). 55296 B -> 3 CTAs/SM.
extern __shared__ float sm1[];

__global__ void __launch_bounds__(192, 3)
k1_scores(const float* __restrict__ x, const float* __restrict__ gw) {
    const int b   = blockIdx.x;
    const int tid = threadIdx.x;
    const int p   = blockIdx.y * 192 + tid;
    float* s_wt = sm1;

    const size_t xb = (size_t)b * NTOK * DD;

    for (int i = tid; i < DD * NG; i += 192) {
        int d = i / NG, g = i % NG;
        s_wt[g * DD + d] = gw[i];
    }
    for (int i = tid; i < DD; i += 192) s_wt[NG * DD + i] = x[xb + i];
    __syncthreads();

    const float4* xr = reinterpret_cast<const float4*>(x + xb + (size_t)(1 + p) * DD);
    ull acc[NGC];
#pragma unroll
    for (int g = 0; g < NGC; ++g) acc[g] = 0ull;
    ull nr = 0ull;

    // distance-2 pipeline: 2 double-float4 buffers, unroll 2 (proven in R2)
    float4 bA0 = xr[0], bA1 = xr[1], bB0 = xr[2], bB1 = xr[3];
#pragma unroll 2
    for (int it = 0; it < DD / 8; ++it) {
        float4 v0, v1;
        if ((it & 1) == 0) { v0 = bA0; v1 = bA1;
            if (it + 2 < DD / 8) { bA0 = xr[2 * it + 4]; bA1 = xr[2 * it + 5]; } }
        else               { v0 = bB0; v1 = bB1;
            if (it + 2 < DD / 8) { bB0 = xr[2 * it + 4]; bB1 = xr[2 * it + 5]; } }
        ull xa01 = pk2(v0.x, v0.y), xa23 = pk2(v0.z, v0.w);
        ull xb01 = pk2(v1.x, v1.y), xb23 = pk2(v1.z, v1.w);
        const float* wd = s_wt + it * 8;
#pragma unroll
        for (int g = 0; g < NGC; ++g) {
            const ulonglong2* wp = reinterpret_cast<const ulonglong2*>(wd + g * DD);
            ulonglong2 w0 = wp[0], w1 = wp[1];
            fma2(acc[g], xa01, w0.x); fma2(acc[g], xa23, w0.y);
            fma2(acc[g], xb01, w1.x); fma2(acc[g], xb23, w1.y);
        }
        fma2(nr, xa01, xa01); fma2(nr, xa23, xa23);
        fma2(nr, xb01, xb01); fma2(nr, xb23, xb23);
    }
#pragma unroll
    for (int g = 0; g < NG; ++g)
        g_scores[((size_t)b * NG + g) * NP + p] = hadd2(acc[g]);
    // cls-norm factor dropped: positive per-batch constant, ordering-invariant
    g_sim[(size_t)b * NP + p] = hadd2(acc[NG]) / fmaxf(sqrtf(hadd2(nr)), 1e-12f);
}

// ==================== K2: topk + softmax + attn output ====================
// grid NB, block 576. smem: sim 576 + mask 576.
extern __shared__ float sm2[];

__global__ void __launch_bounds__(576, 1)
k2_topk_softmax(float* __restrict__ out) {
    const int b   = blockIdx.x;
    const int tid = threadIdx.x;
    float* s_sim  = sm2;
    float* s_mask = sm2 + NP;

    s_sim[tid]  = g_sim[(size_t)b * NP + tid];
    s_mask[tid] = 1.0f;
    __syncthreads();

    if (tid < 32) {
        for (int k = 0; k < NOCC; ++k) {
            float best = 3.4e38f; int bi = NP;
#pragma unroll
            for (int q = 0; q < NP / 32; ++q) {
                int idx = tid + q * 32;
                float v = s_sim[idx];
                if (v < best || (v == best && idx < bi)) { best = v; bi = idx; }
            }
#pragma unroll
            for (int off = 16; off; off >>= 1) {
                float ov = __shfl_down_sync(0xffffffffu, best, off);
                int   oi = __shfl_down_sync(0xffffffffu, bi, off);
                if (ov < best || (ov == best && oi < bi)) { best = ov; bi = oi; }
            }
            bi = __shfl_sync(0xffffffffu, bi, 0);
            if (tid == 0) { s_sim[bi] = 3.4e38f; s_mask[bi] = 0.0f; }
            __syncwarp();
        }
    }
    __syncthreads();

    const int p = tid;
    const float mk = s_mask[p];
    float tv[NG];
    float m = -3.4e38f;
#pragma unroll
    for (int g = 0; g < NG; ++g) {
        tv[g] = g_scores[((size_t)b * NG + g) * NP + p] * 10.0f;
        m = fmaxf(m, tv[g]);
    }
    float ssum = 0.f;
#pragma unroll
    for (int g = 0; g < NG; ++g) { tv[g] = __expf(tv[g] - m); ssum += tv[g]; }
    const float inv = 1.0f / ssum;
    float* oat = out + (size_t)NB * NGC * DD + (size_t)b * NG * NP;
#pragma unroll
    for (int g = 0; g < NG; ++g) {
        float a = tv[g] * inv;
        oat[g * NP + p] = (mk != 0.f) ? a : (1.0f / 17.0f);
        g_scores[((size_t)b * NG + g) * NP + p] = (mk != 0.f) ? a : 0.f;
    }
}

// ======================= K3: group features + cls =========================
// grid (NB, 3), block 256. Thread owns column d = by*256+tid.
// smem: masked attn [17][576] = 39168 B -> 3+ CTAs/SM.
extern __shared__ float sm3[];

__global__ void __launch_bounds__(256, 3)
k3_features(const float* __restrict__ x, float* __restrict__ out) {
    const int b   = blockIdx.x;
    const int tid = threadIdx.x;
    const int d   = blockIdx.y * 256 + tid;
    float* s_at = sm3;

    for (int i = tid; i < NG * NP; i += 256)
        s_at[i] = g_scores[(size_t)b * NG * NP + i];
    __syncthreads();

    const size_t xb = (size_t)b * NTOK * DD;
    const float* xp = x + xb + DD + d;
    ull acc[NG];
#pragma unroll
    for (int g = 0; g < NG; ++g) acc[g] = 0ull;

    // distance-2 rolling prefetch, 4 patches per step, 2 buffers
    float A0 = xp[0], A1 = xp[(size_t)1 * DD], A2 = xp[(size_t)2 * DD], A3 = xp[(size_t)3 * DD];
    float B0 = xp[(size_t)4 * DD], B1 = xp[(size_t)5 * DD], B2 = xp[(size_t)6 * DD], B3 = xp[(size_t)7 * DD];

#pragma unroll 2
    for (int s = 0; s < NP / 4; ++s) {
        float c0, c1, c2, c3;
        if ((s & 1) == 0) {
            c0 = A0; c1 = A1; c2 = A2; c3 = A3;
            if (s + 2 < NP / 4) {
                A0 = xp[(size_t)(4 * s +  8) * DD]; A1 = xp[(size_t)(4 * s +  9) * DD];
                A2 = xp[(size_t)(4 * s + 10) * DD]; A3 = xp[(size_t)(4 * s + 11) * DD];
            }
        } else {
            c0 = B0; c1 = B1; c2 = B2; c3 = B3;
            if (s + 2 < NP / 4) {
                B0 = xp[(size_t)(4 * s +  8) * DD]; B1 = xp[(size_t)(4 * s +  9) * DD];
                B2 = xp[(size_t)(4 * s + 10) * DD]; B3 = xp[(size_t)(4 * s + 11) * DD];
            }
        }
        ull x01 = pk2(c0, c1), x23 = pk2(c2, c3);
        const float* ap = s_at + 4 * s;
#pragma unroll
        for (int g = 0; g < NG; ++g) {
            ulonglong2 at = *reinterpret_cast<const ulonglong2*>(ap + g * NP);
            fma2(acc[g], x01, at.x);
            fma2(acc[g], x23, at.y);
        }
    }

    float* ob = out + (size_t)b * NGC * DD;
    ob[d] = x[xb + d];                        // feats[b][0][d] = cls
#pragma unroll
    for (int g = 0; g < NG; ++g)
        ob[(size_t)(1 + g) * DD + d] = hadd2(acc[g]);
}

extern "C" void kernel_launch(void* const* d_in, const int* in_sizes, int n_in,
                              void* d_out, int out_size) {
    const float* x  = (const float*)d_in[0];
    const float* gw = (const float*)d_in[1];
    float* out = (float*)d_out;

    static bool inited = false;
    if (!inited) {
        cudaFuncSetAttribute(k1_scores, cudaFuncAttributeMaxDynamicSharedMemorySize,
                             NGC * DD * 4);
        cudaFuncSetAttribute(k2_topk_softmax, cudaFuncAttributeMaxDynamicSharedMemorySize,
                             2 * NP * 4);
        cudaFuncSetAttribute(k3_features, cudaFuncAttributeMaxDynamicSharedMemorySize,
                             NG * NP * 4);
        inited = true;
    }

    k1_scores<<<dim3(NB, 3), 192, NGC * DD * 4>>>(x, gw);
    k2_topk_softmax<<<NB, 576, 2 * NP * 4>>>(out);
    k3_features<<<dim3(NB, 3), 256, NG * NP * 4>>>(x, out);
}

// round 5
// speedup vs baseline: 2.0368x; 1.3818x over previous
#include <cuda_runtime.h>
#include <cstdint>
#include <math.h>

#define NB 128
#define NTOK 577
#define NP 576
#define DD 768
#define NG 17
#define NGC 18          // 17 groups + cls row
#define NOCC 10

typedef unsigned long long ull;

// ---- packed f32x2 helpers (sm_103a) ----
__device__ __forceinline__ ull pk2(float a, float b) {
    ull r; asm("mov.b64 %0, {%1,%2};" : "=l"(r) : "f"(a), "f"(b)); return r;
}
__device__ __forceinline__ void fma2(ull &acc, ull a, ull b) {
    asm("fma.rn.f32x2 %0, %1, %2, %0;" : "+l"(acc) : "l"(a), "l"(b));
}
__device__ __forceinline__ float hadd2(ull a) {
    return __uint_as_float((unsigned)a) + __uint_as_float((unsigned)(a >> 32));
}
__device__ __forceinline__ void cpasync16(uint32_t dst, const void* src) {
    asm volatile("cp.async.cg.shared.global [%0], [%1], 16;"
                 :: "r"(dst), "l"(src) : "memory");
}

// scratch (device globals; no allocation)
__device__ float g_scores[(size_t)NB * NG * NP];   // raw scores, then masked attn
__device__ float g_sim[(size_t)NB * NP];

// ============================ K1: scores + sim ============================
// grid NB, block 288 (9 warps). Warp w owns patches [64w, 64w+64); lane l
// computes p0 = 64w+l, p1 = 64w+32+l. x staged into warp-private smem tiles
// via cp.async (coalesced), double-buffered; W^T broadcast from smem.
#define K1_THREADS 288
#define TILE_D 32
#define NT (DD / TILE_D)      // 24
#define WROWS 64
#define PITCH 36              // floats per row: conflict-free 16B LDS (9l+blk mod 8)
#define TILE_FLOATS (WROWS * PITCH)          // 2304
#define OFF_W (9 * 2 * TILE_FLOATS)          // tiles first: 41472 floats
#define K1_SMEM_FLOATS (OFF_W + NGC * DD)    // 41472 + 13824 = 55296 (221184 B)

extern __shared__ float sm1[];

__global__ void __launch_bounds__(K1_THREADS, 1)
k1_scores(const float* __restrict__ x, const float* __restrict__ gw) {
    const int b   = blockIdx.x;
    const int tid = threadIdx.x;
    const int w   = tid >> 5, ln = tid & 31;
    float* s_w = sm1 + OFF_W;

    const size_t xb = (size_t)b * NTOK * DD;

    // stage W^T ([g][d]) + cls as row NG
    for (int i = tid; i < DD * NG; i += K1_THREADS) {
        int d = i / NG, g = i % NG;
        s_w[g * DD + d] = gw[i];
    }
    for (int i = tid; i < DD; i += K1_THREADS) s_w[NG * DD + i] = x[xb + i];

    const uint32_t smem_base = (uint32_t)__cvta_generic_to_shared(sm1);
    const uint32_t buf0 = smem_base + (uint32_t)(w * 2) * TILE_FLOATS * 4;
    const uint32_t buf1 = buf0 + TILE_FLOATS * 4;
    const float* xrow = x + xb + DD + (size_t)(w * WROWS) * DD;  // token 1+64w

    // issue tiles 0 and 1
#pragma unroll
    for (int t = 0; t < 2; ++t) {
        uint32_t dst = t ? buf1 : buf0;
        const float* src = xrow + t * TILE_D;
#pragma unroll
        for (int k = 0; k < 16; ++k) {
            int idx = ln + 32 * k;
            int row = idx >> 3, ch = idx & 7;
            cpasync16(dst + (uint32_t)(row * PITCH + ch * 4) * 4,
                      src + (size_t)row * DD + ch * 4);
        }
        asm volatile("cp.async.commit_group;" ::: "memory");
    }
    __syncthreads();   // W ready (also orders nothing harmful for cp.async)

    ull a0[NGC], a1[NGC], nr0 = 0, nr1 = 0;
#pragma unroll
    for (int g = 0; g < NGC; ++g) { a0[g] = 0; a1[g] = 0; }

    for (int t = 0; t < NT; ++t) {
        asm volatile("cp.async.wait_group 1;" ::: "memory");
        __syncwarp();
        const float* xt = sm1 + (size_t)(w * 2 + (t & 1)) * TILE_FLOATS;
        const float* wd0 = s_w + t * TILE_D;
#pragma unroll
        for (int blk = 0; blk < 8; ++blk) {
            ulonglong2 xv0 = *reinterpret_cast<const ulonglong2*>(
                xt + ln * PITCH + blk * 4);
            ulonglong2 xv1 = *reinterpret_cast<const ulonglong2*>(
                xt + (32 + ln) * PITCH + blk * 4);
            const float* wdb = wd0 + blk * 4;
#pragma unroll
            for (int g = 0; g < NGC; ++g) {
                ulonglong2 wv = *reinterpret_cast<const ulonglong2*>(wdb + g * DD);
                fma2(a0[g], xv0.x, wv.x); fma2(a0[g], xv0.y, wv.y);
                fma2(a1[g], xv1.x, wv.x); fma2(a1[g], xv1.y, wv.y);
            }
            fma2(nr0, xv0.x, xv0.x); fma2(nr0, xv0.y, xv0.y);
            fma2(nr1, xv1.x, xv1.x); fma2(nr1, xv1.y, xv1.y);
        }
        __syncwarp();   // all lanes done reading this buffer before overwrite
        if (t + 2 < NT) {
            uint32_t dst = (t & 1) ? buf1 : buf0;
            const float* src = xrow + (t + 2) * TILE_D;
#pragma unroll
            for (int k = 0; k < 16; ++k) {
                int idx = ln + 32 * k;
                int row = idx >> 3, ch = idx & 7;
                cpasync16(dst + (uint32_t)(row * PITCH + ch * 4) * 4,
                          src + (size_t)row * DD + ch * 4);
            }
        }
        asm volatile("cp.async.commit_group;" ::: "memory");  // (empty group ok on tail)
    }

    const int p0 = w * WROWS + ln, p1 = p0 + 32;
#pragma unroll
    for (int g = 0; g < NG; ++g) {
        g_scores[((size_t)b * NG + g) * NP + p0] = hadd2(a0[g]);
        g_scores[((size_t)b * NG + g) * NP + p1] = hadd2(a1[g]);
    }
    // cls-norm factor dropped: positive per-batch constant, ordering-invariant
    g_sim[(size_t)b * NP + p0] = hadd2(a0[NG]) / fmaxf(sqrtf(hadd2(nr0)), 1e-12f);
    g_sim[(size_t)b * NP + p1] = hadd2(a1[NG]) / fmaxf(sqrtf(hadd2(nr1)), 1e-12f);
}

// ==================== K2: topk + softmax + attn output ====================
extern __shared__ float sm2[];

__global__ void __launch_bounds__(576, 1)
k2_topk_softmax(float* __restrict__ out) {
    const int b   = blockIdx.x;
    const int tid = threadIdx.x;
    float* s_sim  = sm2;
    float* s_mask = sm2 + NP;

    s_sim[tid]  = g_sim[(size_t)b * NP + tid];
    s_mask[tid] = 1.0f;
    __syncthreads();

    if (tid < 32) {
        for (int k = 0; k < NOCC; ++k) {
            float best = 3.4e38f; int bi = NP;
#pragma unroll
            for (int q = 0; q < NP / 32; ++q) {
                int idx = tid + q * 32;
                float v = s_sim[idx];
                if (v < best || (v == best && idx < bi)) { best = v; bi = idx; }
            }
#pragma unroll
            for (int off = 16; off; off >>= 1) {
                float ov = __shfl_down_sync(0xffffffffu, best, off);
                int   oi = __shfl_down_sync(0xffffffffu, bi, off);
                if (ov < best || (ov == best && oi < bi)) { best = ov; bi = oi; }
            }
            bi = __shfl_sync(0xffffffffu, bi, 0);
            if (tid == 0) { s_sim[bi] = 3.4e38f; s_mask[bi] = 0.0f; }
            __syncwarp();
        }
    }
    __syncthreads();

    const int p = tid;
    const float mk = s_mask[p];
    float tv[NG];
    float m = -3.4e38f;
#pragma unroll
    for (int g = 0; g < NG; ++g) {
        tv[g] = g_scores[((size_t)b * NG + g) * NP + p] * 10.0f;
        m = fmaxf(m, tv[g]);
    }
    float ssum = 0.f;
#pragma unroll
    for (int g = 0; g < NG; ++g) { tv[g] = __expf(tv[g] - m); ssum += tv[g]; }
    const float inv = 1.0f / ssum;
    float* oat = out + (size_t)NB * NGC * DD + (size_t)b * NG * NP;
#pragma unroll
    for (int g = 0; g < NG; ++g) {
        float a = tv[g] * inv;
        oat[g * NP + p] = (mk != 0.f) ? a : (1.0f / 17.0f);
        g_scores[((size_t)b * NG + g) * NP + p] = (mk != 0.f) ? a : 0.f;
    }
}

// ======================= K3: group features + cls =========================
extern __shared__ float sm3[];

__global__ void __launch_bounds__(256, 3)
k3_features(const float* __restrict__ x, float* __restrict__ out) {
    const int b   = blockIdx.x;
    const int tid = threadIdx.x;
    const int d   = blockIdx.y * 256 + tid;
    float* s_at = sm3;

    for (int i = tid; i < NG * NP; i += 256)
        s_at[i] = g_scores[(size_t)b * NG * NP + i];
    __syncthreads();

    const size_t xb = (size_t)b * NTOK * DD;
    const float* xp = x + xb + DD + d;
    ull acc[NG];
#pragma unroll
    for (int g = 0; g < NG; ++g) acc[g] = 0ull;

    float A0 = xp[0], A1 = xp[(size_t)1 * DD], A2 = xp[(size_t)2 * DD], A3 = xp[(size_t)3 * DD];
    float B0 = xp[(size_t)4 * DD], B1 = xp[(size_t)5 * DD], B2 = xp[(size_t)6 * DD], B3 = xp[(size_t)7 * DD];

#pragma unroll 2
    for (int s = 0; s < NP / 4; ++s) {
        float c0, c1, c2, c3;
        if ((s & 1) == 0) {
            c0 = A0; c1 = A1; c2 = A2; c3 = A3;
            if (s + 2 < NP / 4) {
                A0 = xp[(size_t)(4 * s +  8) * DD]; A1 = xp[(size_t)(4 * s +  9) * DD];
                A2 = xp[(size_t)(4 * s + 10) * DD]; A3 = xp[(size_t)(4 * s + 11) * DD];
            }
        } else {
            c0 = B0; c1 = B1; c2 = B2; c3 = B3;
            if (s + 2 < NP / 4) {
                B0 = xp[(size_t)(4 * s +  8) * DD]; B1 = xp[(size_t)(4 * s +  9) * DD];
                B2 = xp[(size_t)(4 * s + 10) * DD]; B3 = xp[(size_t)(4 * s + 11) * DD];
            }
        }
        ull x01 = pk2(c0, c1), x23 = pk2(c2, c3);
        const float* ap = s_at + 4 * s;
#pragma unroll
        for (int g = 0; g < NG; ++g) {
            ulonglong2 at = *reinterpret_cast<const ulonglong2*>(ap + g * NP);
            fma2(acc[g], x01, at.x);
            fma2(acc[g], x23, at.y);
        }
    }

    float* ob = out + (size_t)b * NGC * DD;
    ob[d] = x[xb + d];                        // feats[b][0][d] = cls
#pragma unroll
    for (int g = 0; g < NG; ++g)
        ob[(size_t)(1 + g) * DD + d] = hadd2(acc[g]);
}

extern "C" void kernel_launch(void* const* d_in, const int* in_sizes, int n_in,
                              void* d_out, int out_size) {
    const float* x  = (const float*)d_in[0];
    const float* gw = (const float*)d_in[1];
    float* out = (float*)d_out;

    static bool inited = false;
    if (!inited) {
        cudaFuncSetAttribute(k1_scores, cudaFuncAttributeMaxDynamicSharedMemorySize,
                             K1_SMEM_FLOATS * 4);
        cudaFuncSetAttribute(k2_topk_softmax, cudaFuncAttributeMaxDynamicSharedMemorySize,
                             2 * NP * 4);
        cudaFuncSetAttribute(k3_features, cudaFuncAttributeMaxDynamicSharedMemorySize,
                             NG * NP * 4);
        inited = true;
    }

    k1_scores<<<NB, K1_THREADS, K1_SMEM_FLOATS * 4>>>(x, gw);
    k2_topk_softmax<<<NB, 576, 2 * NP * 4>>>(out);
    k3_features<<<dim3(NB, 3), 256, NG * NP * 4>>>(x, out);
}